// round 16
// baseline (speedup 1.0000x reference)
#include <cuda_runtime.h>
#include <cuda_bf16.h>

// Dequantize: out4[g] = codebooks[cb][code[g]] * scales[g/16]
//   cb = (g >= N_codes/2) ? 1 : 0   (codes buffer is [2, N/2] contiguous)
//
// Persistent grid-stride version (R12: occ=89%, issue=15%, nothing saturated
// -> limiter = wave transitions + unhidden DRAM latency per short CTA):
//   - ~1184 CTAs (one wave) loop over 2048-code tiles
//   - software pipeline: next tile's 8 code LDGs issued before current tile's
//     gather/scale/store, hiding DRAM latency behind L1 work
//   - all global accesses fully coalesced; output streaming (__stcs)

#define TPB   256
#define KPT   8
#define TILE  (TPB * KPT)

__global__ __launch_bounds__(TPB)
void dequant_kernel(const float4* __restrict__ codebooks,   // 512 x float4
                    const float*  __restrict__ scales,
                    const int*    __restrict__ codes,        // N codes (i32)
                    float4*       __restrict__ out,          // N float4
                    int n_codes,
                    int half_codes,
                    int n_full)                              // full tiles
{
    __shared__ float4 cb[512];

    #pragma unroll
    for (int i = threadIdx.x; i < 512; i += TPB)
        cb[i] = codebooks[i];
    __syncthreads();

    int tile = blockIdx.x;
    int base = tile * TILE + threadIdx.x;

    int c_cur[KPT];
    if (tile < n_full) {
        #pragma unroll
        for (int k = 0; k < KPT; k++)
            c_cur[k] = __ldcs(&codes[base + k * TPB]);
    }

    while (tile < n_full) {
        // ---- prefetch next tile's codes (hidden behind this tile's work) ----
        const int ntile = tile + gridDim.x;
        const int nbase = ntile * TILE + threadIdx.x;
        int c_nxt[KPT];
        if (ntile < n_full) {
            #pragma unroll
            for (int k = 0; k < KPT; k++)
                c_nxt[k] = __ldcs(&codes[nbase + k * TPB]);
        }

        // ---- process current tile ----
        #pragma unroll
        for (int k = 0; k < KPT; k++) {
            const int idx = base + k * TPB;
            const float  s = scales[idx >> 4];   // cached: line shared across warps
            const float4 v = cb[c_cur[k] + ((idx >= half_codes) ? 256 : 0)];
            float4 o;
            o.x = v.x * s;
            o.y = v.y * s;
            o.z = v.z * s;
            o.w = v.w * s;
            __stcs(&out[(size_t)idx], o);
        }

        tile = ntile;
        base = nbase;
        #pragma unroll
        for (int k = 0; k < KPT; k++)
            c_cur[k] = c_nxt[k];
    }

    // ---- tail: codes beyond the last full tile ----
    const int tail_lo = n_full * TILE;
    for (int idx = tail_lo + blockIdx.x * TPB + threadIdx.x;
         idx < n_codes;
         idx += gridDim.x * TPB) {
        const int   cc = __ldcs(&codes[idx]) + ((idx >= half_codes) ? 256 : 0);
        const float ss = scales[idx >> 4];
        const float4 v = cb[cc];
        float4 o;
        o.x = v.x * ss;
        o.y = v.y * ss;
        o.z = v.z * ss;
        o.w = v.w * ss;
        __stcs(&out[(size_t)idx], o);
    }
}

extern "C" void kernel_launch(void* const* d_in, const int* in_sizes, int n_in,
                              void* d_out, int out_size)
{
    // metadata order: codebooks (f32), scales (f32), codes (i32), rows, columns
    const float4* codebooks = (const float4*)d_in[0];
    const float*  scales    = (const float*) d_in[1];
    const int*    codes     = (const int*)   d_in[2];
    float4*       out       = (float4*)      d_out;

    const int n_codes = in_sizes[2];     // numel / 4  (both codebooks)
    const int half    = n_codes / 2;
    const int n_full  = n_codes / TILE;

    int grid = 148 * 8;                  // one full wave of persistent CTAs
    if (grid > n_full) grid = (n_full > 0) ? n_full : 1;

    dequant_kernel<<<grid, TPB>>>(codebooks, scales, codes, out,
                                  n_codes, half, n_full);
}

// round 17
// speedup vs baseline: 1.0802x; 1.0802x over previous
#include <cuda_runtime.h>
#include <cuda_bf16.h>

// Dequantize: out4[g] = codebooks[cb][code[g]] * scales[g/16]
//   cb = (g >= N_codes/2) ? 1 : 0   (codes buffer is [2, N/2] contiguous)
//
// R12 shape (best: occ 89%, regs 31) + SMEM-staged scales:
//   - one 2048-code tile per CTA, KPT=8 block-strided, codes front-batched
//   - the tile's 128 scales staged into SMEM by one coalesced load; per-k
//     scale read becomes a conflict-free LDS broadcast (removes the serial
//     per-iteration LDG latency chain that R12 still had)
//   - __launch_bounds__(256, 8) keeps 8 CTAs/SM
//   - all global accesses fully coalesced; output streaming (__stcs)

#define TPB   256
#define KPT   8
#define TILE  (TPB * KPT)          // 2048 codes
#define NSCL  (TILE / 16)          // 128 scales per tile

__global__ __launch_bounds__(TPB, 8)
void dequant_kernel(const float4* __restrict__ codebooks,   // 512 x float4
                    const float*  __restrict__ scales,
                    const int*    __restrict__ codes,        // N codes (i32)
                    float4*       __restrict__ out,          // N float4
                    int n_codes,
                    int half_codes)
{
    __shared__ float4 cb[512];
    __shared__ float  ssc[NSCL];

    const int tid     = threadIdx.x;
    const int tile_lo = blockIdx.x * TILE;
    const int base    = tile_lo + tid;

    const bool full     = (tile_lo + TILE <= n_codes);
    const bool straddle = (tile_lo < half_codes) && (tile_lo + TILE > half_codes);

    // ---- front-batch this thread's codes (issue before SMEM staging) ----
    int c[KPT];
    if (full) {
        #pragma unroll
        for (int k = 0; k < KPT; k++)
            c[k] = __ldcs(&codes[base + k * TPB]);
    }

    // ---- stage codebook (8KB) and this tile's scales (512B) ----
    #pragma unroll
    for (int i = tid; i < 512; i += TPB)
        cb[i] = codebooks[i];
    if (full && tid < NSCL)
        ssc[tid] = __ldcs(&scales[(tile_lo >> 4) + tid]);
    __syncthreads();

    if (full && !straddle) {
        // ---- fast path: no bounds predication, uniform codebook half ----
        const int off  = (tile_lo >= half_codes) ? 256 : 0;
        const int slot = tid >> 4;                 // lane group -> scale slot

        #pragma unroll
        for (int k = 0; k < KPT; k++) {
            const float  s = ssc[slot + k * 16];   // LDS broadcast
            const float4 v = cb[c[k] + off];
            float4 o;
            o.x = v.x * s;
            o.y = v.y * s;
            o.z = v.z * s;
            o.w = v.w * s;
            __stcs(&out[(size_t)(base + k * TPB)], o);
        }
    } else {
        // ---- tail / straddle path ----
        #pragma unroll
        for (int k = 0; k < KPT; k++) {
            const int idx = base + k * TPB;
            if (idx < n_codes) {
                const int   cc = __ldcs(&codes[idx]) + ((idx >= half_codes) ? 256 : 0);
                const float ss = scales[idx >> 4];
                const float4 v = cb[cc];
                float4 o;
                o.x = v.x * ss;
                o.y = v.y * ss;
                o.z = v.z * ss;
                o.w = v.w * ss;
                __stcs(&out[(size_t)idx], o);
            }
        }
    }
}

extern "C" void kernel_launch(void* const* d_in, const int* in_sizes, int n_in,
                              void* d_out, int out_size)
{
    // metadata order: codebooks (f32), scales (f32), codes (i32), rows, columns
    const float4* codebooks = (const float4*)d_in[0];
    const float*  scales    = (const float*) d_in[1];
    const int*    codes     = (const int*)   d_in[2];
    float4*       out       = (float4*)      d_out;

    const int n_codes = in_sizes[2];     // numel / 4  (both codebooks)
    const int half    = n_codes / 2;

    const int blocks = (n_codes + TILE - 1) / TILE;

    dequant_kernel<<<blocks, TPB>>>(codebooks, scales, codes, out, n_codes, half);
}